// round 9
// baseline (speedup 1.0000x reference)
#include <cuda_runtime.h>
#include <cstdint>

// Problem constants: G=512, GP=256, keys fit in 24 bits since b==0.
#define NKEYS  (1u << 24)          // 16,777,216 possible parent keys
#define NWORDS (1u << 19)          // bitmap words (32 keys/word)
#define NBLKS  (NWORDS / 1024)     // 512 scan blocks
#define NMAX   4000000
#define NSHARD 4                   // shard = key >> 22; quarter feats ~28MB (L2-resident)

// Scratch (static device globals)
__device__ unsigned g_bitmap[NWORDS];
__device__ unsigned g_wprefix[NWORDS];     // per-word excl popcount prefix (within 1024-word block)
__device__ unsigned g_blocksums[NBLKS];    // 1024-word-block exclusive prefix
__device__ unsigned g_total;               // number of unique keys
__device__ unsigned g_scnt[NSHARD];        // shard cursors
__device__ uint2    g_shard[NSHARD][NMAX]; // {(key<<3)|off, feat bits} per shard

__global__ void k_zero_meta() {
    unsigned i = blockIdx.x * blockDim.x + threadIdx.x;
    if (i < NWORDS / 4) reinterpret_cast<uint4*>(g_bitmap)[i] = make_uint4(0, 0, 0, 0);
    if (i < NSHARD) g_scnt[i] = 0;
}

// ---------------------------------------------------------------------------
// Pass 1: key+offset, presence bit, and route {comb, feat} into its key-quarter
// shard via warp-aggregated cursors (one atomicAdd per warp per shard).
// ---------------------------------------------------------------------------
__global__ void k_build(const int4* __restrict__ coords,
                        const float* __restrict__ feats, int n) {
    int i = blockIdx.x * blockDim.x + threadIdx.x;
    if (i >= n) return;
    int4 c = coords[i];
    unsigned key = (((unsigned)c.x * 256u + (((unsigned)c.y) >> 1)) * 256u
                    + (((unsigned)c.z) >> 1)) * 256u + (((unsigned)c.w) >> 1);
    unsigned off = (((unsigned)c.y & 1u) << 2) | (((unsigned)c.z & 1u) << 1)
                 | ((unsigned)c.w & 1u);
    unsigned comb = (key << 3) | off;
    atomicOr(&g_bitmap[key >> 5], 1u << (key & 31u));

    float f = feats[i];
    unsigned q = key >> 22;                      // 0..3
    unsigned active = __activemask();
    unsigned peers  = __match_any_sync(active, q);
    int leader = __ffs(peers) - 1;
    int lane   = threadIdx.x & 31;
    unsigned base = 0;
    if (lane == leader) base = atomicAdd(&g_scnt[q], (unsigned)__popc(peers));
    base = __shfl_sync(peers, base, leader);
    unsigned pos = base + (unsigned)__popc(peers & ((1u << lane) - 1u));
    g_shard[q][pos] = make_uint2(comb, __float_as_uint(f));
}

// ---------------------------------------------------------------------------
// Pass 2a: per-1024-word-block exclusive scan of bitmap popcounts.
// ---------------------------------------------------------------------------
__global__ void k_scan_words() {
    __shared__ unsigned warp_sums[32];
    unsigned w = blockIdx.x * 1024u + threadIdx.x;
    unsigned c = __popc(g_bitmap[w]);
    unsigned v = c;
    #pragma unroll
    for (int d = 1; d < 32; d <<= 1) {
        unsigned t = __shfl_up_sync(0xFFFFFFFFu, v, d);
        if ((threadIdx.x & 31u) >= (unsigned)d) v += t;
    }
    if ((threadIdx.x & 31u) == 31u) warp_sums[threadIdx.x >> 5] = v;
    __syncthreads();
    if (threadIdx.x < 32) {
        unsigned s = warp_sums[threadIdx.x];
        #pragma unroll
        for (int d = 1; d < 32; d <<= 1) {
            unsigned t = __shfl_up_sync(0xFFFFFFFFu, s, d);
            if (threadIdx.x >= (unsigned)d) s += t;
        }
        warp_sums[threadIdx.x] = s;
    }
    __syncthreads();
    unsigned warp_off = (threadIdx.x >= 32) ? warp_sums[(threadIdx.x >> 5) - 1] : 0u;
    g_wprefix[w] = warp_off + v - c;
    if (threadIdx.x == 1023) g_blocksums[blockIdx.x] = warp_off + v;
}

// ---------------------------------------------------------------------------
// Pass 2b: exclusive scan of 512 block totals; publish g_total.
// ---------------------------------------------------------------------------
__global__ void k_scan_blocks() {
    __shared__ unsigned warp_sums[16];
    unsigned c = g_blocksums[threadIdx.x];
    unsigned v = c;
    #pragma unroll
    for (int d = 1; d < 32; d <<= 1) {
        unsigned t = __shfl_up_sync(0xFFFFFFFFu, v, d);
        if ((threadIdx.x & 31u) >= (unsigned)d) v += t;
    }
    if ((threadIdx.x & 31u) == 31u) warp_sums[threadIdx.x >> 5] = v;
    __syncthreads();
    if (threadIdx.x < 16) {
        unsigned s = warp_sums[threadIdx.x];
        #pragma unroll
        for (int d = 1; d < 16; d <<= 1) {
            unsigned t = __shfl_up_sync(0xFFFFu, s, d);
            if (threadIdx.x >= (unsigned)d) s += t;
        }
        warp_sums[threadIdx.x] = s;
    }
    __syncthreads();
    unsigned warp_off = (threadIdx.x >= 32) ? warp_sums[(threadIdx.x >> 5) - 1] : 0u;
    g_blocksums[threadIdx.x] = warp_off + v - c;
    if (threadIdx.x == NBLKS - 1) g_total = warp_off + v;
}

// ---------------------------------------------------------------------------
// Pass 3 (per key quarter): emit sorted unique coords (float32) AND zero the
// row's feats — warms L2 with exactly the lines the quarter's scatter hits.
// ---------------------------------------------------------------------------
__global__ void k_coords_q(float4* __restrict__ out_coords,
                           float4* __restrict__ out_feats4, unsigned keybase) {
    unsigned k = keybase + blockIdx.x * blockDim.x + threadIdx.x;
    unsigned w    = k >> 5;
    unsigned bit  = k & 31u;
    unsigned word = g_bitmap[w];
    if (!((word >> bit) & 1u)) return;
    unsigned rank = g_wprefix[w] + g_blocksums[w >> 10]
                  + (unsigned)__popc(word & ((1u << bit) - 1u));
    out_coords[rank] = make_float4((float)(k >> 24), (float)((k >> 16) & 255u),
                                   (float)((k >> 8) & 255u), (float)(k & 255u));
    out_feats4[(size_t)rank * 2]     = make_float4(0.f, 0.f, 0.f, 0.f);
    out_feats4[(size_t)rank * 2 + 1] = make_float4(0.f, 0.f, 0.f, 0.f);
}

// ---------------------------------------------------------------------------
// Pass 4 (per key quarter): consume shard entries, rank + atomicAdd.
// Target region ~28MB feats, just zero-warmed -> L2-resident RMW.
// ---------------------------------------------------------------------------
__global__ void k_scatter_q(float* __restrict__ out_feats, int q) {
    unsigned cnt = g_scnt[q];
    for (unsigned i = blockIdx.x * blockDim.x + threadIdx.x; i < cnt;
         i += gridDim.x * blockDim.x) {
        uint2 e = g_shard[q][i];
        unsigned key  = e.x >> 3;
        unsigned off  = e.x & 7u;
        unsigned w    = key >> 5;
        unsigned bit  = key & 31u;
        unsigned word = g_bitmap[w];
        unsigned rank = g_wprefix[w] + g_blocksums[w >> 10]
                      + (unsigned)__popc(word & ((1u << bit) - 1u));
        atomicAdd(&out_feats[(size_t)rank * 8u + off], __uint_as_float(e.y));
    }
}

// ---------------------------------------------------------------------------
// Pass 5: invalid tail rows (rank >= g_total): coords=-1, feats=0.
// Disjoint from valid-row writes; runs right after the scan.
// ---------------------------------------------------------------------------
__global__ void k_fill_invalid(float4* __restrict__ out_coords,
                               float4* __restrict__ out_feats4, int n) {
    int i = blockIdx.x * blockDim.x + threadIdx.x;
    if (i >= n || (unsigned)i < g_total) return;
    out_coords[i] = make_float4(-1.f, -1.f, -1.f, -1.f);
    out_feats4[(size_t)i * 2]     = make_float4(0.f, 0.f, 0.f, 0.f);
    out_feats4[(size_t)i * 2 + 1] = make_float4(0.f, 0.f, 0.f, 0.f);
}

extern "C" void kernel_launch(void* const* d_in, const int* in_sizes, int n_in,
                              void* d_out, int out_size) {
    const int4*  coords = (const int4*)d_in[0];
    const float* feats  = (const float*)d_in[1];
    int n = in_sizes[0] / 4;   // N points

    float4* out_coords = (float4*)d_out;
    float*  out_feats  = (float*)((char*)d_out + (size_t)n * 4 * sizeof(float));
    float4* out_feats4 = (float4*)out_feats;

    k_zero_meta  <<<((NWORDS / 4) + 255) / 256, 256>>>();
    k_build      <<<(n + 255) / 256, 256>>>(coords, feats, n);
    k_scan_words <<<NBLKS, 1024>>>();
    k_scan_blocks<<<1, NBLKS>>>();
    k_fill_invalid<<<(n + 255) / 256, 256>>>(out_coords, out_feats4, n);
    for (int q = 0; q < NSHARD; q++) {
        k_coords_q <<<(NKEYS / NSHARD) / 256, 256>>>(out_coords, out_feats4,
                                                     (unsigned)q << 22);
        k_scatter_q<<<2048, 256>>>(out_feats, q);
    }
}

// round 10
// speedup vs baseline: 1.3682x; 1.3682x over previous
#include <cuda_runtime.h>
#include <cstdint>

// Problem constants: G=512, GP=256, keys fit in 24 bits since b==0.
#define NKEYS  (1u << 24)          // 16,777,216 possible parent keys
#define NWORDS (1u << 19)          // bitmap words (32 keys/word)
#define NBLKS  (NWORDS / 1024)     // 512 scan blocks
#define NMAX   4000000
#define NQ     4                   // key quarters: quarter feats ~28MB -> L2-resident

// Scratch (static device globals)
__device__ unsigned g_bitmap[NWORDS];
__device__ unsigned g_wprefix[NWORDS];    // per-word excl popcount prefix (within 1024-word block)
__device__ unsigned g_blocksums[NBLKS];   // 1024-word-block exclusive prefix
__device__ unsigned g_total;              // number of unique keys
__device__ unsigned g_combined[NMAX];     // (key<<3)|offset per point

__global__ void k_zero_bitmap() {
    unsigned i = blockIdx.x * blockDim.x + threadIdx.x;
    if (i < NWORDS / 4) reinterpret_cast<uint4*>(g_bitmap)[i] = make_uint4(0, 0, 0, 0);
}

// ---------------------------------------------------------------------------
// Pass 1: per point, compute key + child-offset, mark presence bit.
// ---------------------------------------------------------------------------
__global__ void k_build(const int4* __restrict__ coords, int n) {
    int i = blockIdx.x * blockDim.x + threadIdx.x;
    if (i >= n) return;
    int4 c = coords[i];
    unsigned key = (((unsigned)c.x * 256u + (((unsigned)c.y) >> 1)) * 256u
                    + (((unsigned)c.z) >> 1)) * 256u + (((unsigned)c.w) >> 1);
    unsigned off = (((unsigned)c.y & 1u) << 2) | (((unsigned)c.z & 1u) << 1)
                 | ((unsigned)c.w & 1u);
    g_combined[i] = (key << 3) | off;
    atomicOr(&g_bitmap[key >> 5], 1u << (key & 31u));
}

// ---------------------------------------------------------------------------
// Pass 2a: per-1024-word-block exclusive scan of bitmap popcounts.
// ---------------------------------------------------------------------------
__global__ void k_scan_words() {
    __shared__ unsigned warp_sums[32];
    unsigned w = blockIdx.x * 1024u + threadIdx.x;
    unsigned c = __popc(g_bitmap[w]);
    unsigned v = c;
    #pragma unroll
    for (int d = 1; d < 32; d <<= 1) {
        unsigned t = __shfl_up_sync(0xFFFFFFFFu, v, d);
        if ((threadIdx.x & 31u) >= (unsigned)d) v += t;
    }
    if ((threadIdx.x & 31u) == 31u) warp_sums[threadIdx.x >> 5] = v;
    __syncthreads();
    if (threadIdx.x < 32) {
        unsigned s = warp_sums[threadIdx.x];
        #pragma unroll
        for (int d = 1; d < 32; d <<= 1) {
            unsigned t = __shfl_up_sync(0xFFFFFFFFu, s, d);
            if (threadIdx.x >= (unsigned)d) s += t;
        }
        warp_sums[threadIdx.x] = s;
    }
    __syncthreads();
    unsigned warp_off = (threadIdx.x >= 32) ? warp_sums[(threadIdx.x >> 5) - 1] : 0u;
    g_wprefix[w] = warp_off + v - c;
    if (threadIdx.x == 1023) g_blocksums[blockIdx.x] = warp_off + v;
}

// ---------------------------------------------------------------------------
// Pass 2b: exclusive scan of 512 block totals; publish g_total.
// ---------------------------------------------------------------------------
__global__ void k_scan_blocks() {
    __shared__ unsigned warp_sums[16];
    unsigned c = g_blocksums[threadIdx.x];
    unsigned v = c;
    #pragma unroll
    for (int d = 1; d < 32; d <<= 1) {
        unsigned t = __shfl_up_sync(0xFFFFFFFFu, v, d);
        if ((threadIdx.x & 31u) >= (unsigned)d) v += t;
    }
    if ((threadIdx.x & 31u) == 31u) warp_sums[threadIdx.x >> 5] = v;
    __syncthreads();
    if (threadIdx.x < 16) {
        unsigned s = warp_sums[threadIdx.x];
        #pragma unroll
        for (int d = 1; d < 16; d <<= 1) {
            unsigned t = __shfl_up_sync(0xFFFFu, s, d);
            if (threadIdx.x >= (unsigned)d) s += t;
        }
        warp_sums[threadIdx.x] = s;
    }
    __syncthreads();
    unsigned warp_off = (threadIdx.x >= 32) ? warp_sums[(threadIdx.x >> 5) - 1] : 0u;
    g_blocksums[threadIdx.x] = warp_off + v - c;
    if (threadIdx.x == NBLKS - 1) g_total = warp_off + v;
}

// ---------------------------------------------------------------------------
// Pass 3 (per key quarter): emit sorted unique coords (float32, streaming
// stores — never re-read) AND zero the row's feats (normal stores — these are
// exactly the L2 lines the quarter's scatter is about to RMW).
// ---------------------------------------------------------------------------
__global__ void k_coords_q(float4* __restrict__ out_coords,
                           float4* __restrict__ out_feats4, unsigned keybase) {
    unsigned k = keybase + blockIdx.x * blockDim.x + threadIdx.x;
    unsigned w    = k >> 5;
    unsigned bit  = k & 31u;
    unsigned word = g_bitmap[w];
    if (!((word >> bit) & 1u)) return;
    unsigned rank = g_wprefix[w] + g_blocksums[w >> 10]
                  + (unsigned)__popc(word & ((1u << bit) - 1u));
    __stcs(&out_coords[rank],
           make_float4((float)(k >> 24), (float)((k >> 16) & 255u),
                       (float)((k >> 8) & 255u), (float)(k & 255u)));
    out_feats4[(size_t)rank * 2]     = make_float4(0.f, 0.f, 0.f, 0.f);
    out_feats4[(size_t)rank * 2 + 1] = make_float4(0.f, 0.f, 0.f, 0.f);
}

// ---------------------------------------------------------------------------
// Pass 4 (per key quarter): predicated scatter. Streaming reads of combined
// (re-read each quarter; don't pollute L2), atomics hit the ~28MB just-zeroed
// quarter -> L2-resident RMW.
// ---------------------------------------------------------------------------
__global__ void k_scatter_q(const float* __restrict__ feats,
                            float* __restrict__ out_feats, int n, unsigned q) {
    int i = blockIdx.x * blockDim.x + threadIdx.x;
    if (i >= n) return;
    unsigned comb = __ldcs(&g_combined[i]);
    unsigned key  = comb >> 3;
    if ((key >> 22) != q) return;
    unsigned off  = comb & 7u;
    unsigned w    = key >> 5;
    unsigned bit  = key & 31u;
    unsigned word = g_bitmap[w];
    unsigned rank = g_wprefix[w] + g_blocksums[w >> 10]
                  + (unsigned)__popc(word & ((1u << bit) - 1u));
    atomicAdd(&out_feats[(size_t)rank * 8u + off], __ldcs(&feats[i]));
}

// ---------------------------------------------------------------------------
// Pass 5: invalid tail rows (rank >= g_total): coords=-1, feats=0. Streaming
// stores — this region is disjoint from the valid rows the scatters touch.
// ---------------------------------------------------------------------------
__global__ void k_fill_invalid(float4* __restrict__ out_coords,
                               float4* __restrict__ out_feats4, int n) {
    int i = blockIdx.x * blockDim.x + threadIdx.x;
    if (i >= n || (unsigned)i < g_total) return;
    __stcs(&out_coords[i], make_float4(-1.f, -1.f, -1.f, -1.f));
    __stcs(&out_feats4[(size_t)i * 2],     make_float4(0.f, 0.f, 0.f, 0.f));
    __stcs(&out_feats4[(size_t)i * 2 + 1], make_float4(0.f, 0.f, 0.f, 0.f));
}

extern "C" void kernel_launch(void* const* d_in, const int* in_sizes, int n_in,
                              void* d_out, int out_size) {
    const int4*  coords = (const int4*)d_in[0];
    const float* feats  = (const float*)d_in[1];
    int n = in_sizes[0] / 4;   // N points

    float4* out_coords = (float4*)d_out;
    float*  out_feats  = (float*)((char*)d_out + (size_t)n * 4 * sizeof(float));
    float4* out_feats4 = (float4*)out_feats;

    k_zero_bitmap <<<((NWORDS / 4) + 255) / 256, 256>>>();
    k_build       <<<(n + 255) / 256, 256>>>(coords, n);
    k_scan_words  <<<NBLKS, 1024>>>();
    k_scan_blocks <<<1, NBLKS>>>();
    k_fill_invalid<<<(n + 255) / 256, 256>>>(out_coords, out_feats4, n);
    for (unsigned q = 0; q < NQ; q++) {
        k_coords_q <<<(NKEYS / NQ) / 256, 256>>>(out_coords, out_feats4, q << 22);
        k_scatter_q<<<(n + 255) / 256, 256>>>(feats, out_feats, n, q);
    }
}